// round 3
// baseline (speedup 1.0000x reference)
#include <cuda_runtime.h>
#include <cuda_bf16.h>
#include <math.h>

// Problem constants
#define Bb 128
#define Nn 512
#define Ff 128
#define Ll 64
#define Hh 128
#define Cc 10

// ---------------- scratch (device globals; no allocation allowed) ----------------
__device__ float g_inv_deg[Bb * Nn];            // 1/deg[b,k]
__device__ float g_Ys[Bb * Nn * Ll];            // (h @ W_s) / deg    [B,N,L]
__device__ float g_h1[Bb * Nn * Ll];            // elu(g @ Ys + b_s)  [B,N,L]
__device__ float2 g_q[Bb * Nn];                 // (h1@W_mu, h1@W_lv)/deg
__device__ float g_v[Bb * Nn];                  // sigmoid(beta*z)
__device__ float g_vd[Bb * Nn];                 // v / deg
__device__ float g_hp[Bb * Ll];                 // pooled features
__device__ float g_acc[4];                      // [kl_sum, mse_sum, nll_sum, acc_sum]

__device__ __forceinline__ float elu1(float x) { return x > 0.f ? x : expm1f(x); }

// ---------------- K0: zero accumulators ----------------
__global__ void k0_init() {
    if (threadIdx.x < 4) g_acc[threadIdx.x] = 0.f;
}

// ---------------- K1: inverse degrees (column sums of g) ----------------
__global__ void k1_deg(const float* __restrict__ g) {
    int idx = blockIdx.x * blockDim.x + threadIdx.x;   // b*N + n
    if (idx >= Bb * Nn) return;
    int b = idx >> 9;
    int n = idx & (Nn - 1);
    const float* p = g + (size_t)b * Nn * Nn + n;
    float s0 = 0.f, s1 = 0.f, s2 = 0.f, s3 = 0.f;
    #pragma unroll 4
    for (int i = 0; i < Nn; i += 4) {
        s0 += p[(size_t)(i + 0) * Nn];
        s1 += p[(size_t)(i + 1) * Nn];
        s2 += p[(size_t)(i + 2) * Nn];
        s3 += p[(size_t)(i + 3) * Nn];
    }
    g_inv_deg[idx] = 1.f / ((s0 + s1) + (s2 + s3));
}

// ---------------- shared tiled-GEMM parameters ----------------
#define BM 128
#define BN 64
#define BK 16
// 256 threads, each computes 8(m) x 4(n)

// ---------------- K2: Ys = (h @ W_s) * inv_deg   ( [65536,128] @ [128,64] ) -------
__global__ void __launch_bounds__(256) k2_hws(const float* __restrict__ h,
                                              const float* __restrict__ W_s) {
    __shared__ __align__(16) float As[BK][BM + 4];
    __shared__ __align__(16) float Bs[BK][BN];
    int m0 = blockIdx.x * BM;           // row tile into 65536 rows
    int tid = threadIdx.x;
    int tx = tid & 15;                  // n group (4 cols each)
    int ty = tid >> 4;                  // m group (8 rows each)
    float acc[8][4];
    #pragma unroll
    for (int i = 0; i < 8; i++)
        #pragma unroll
        for (int j = 0; j < 4; j++) acc[i][j] = 0.f;

    for (int k0 = 0; k0 < Ff; k0 += BK) {
        #pragma unroll
        for (int jj = 0; jj < 2; jj++) {
            int f4 = tid + 256 * jj;          // 0..511
            int row = f4 >> 2;                // 0..127
            int c4 = f4 & 3;                  // 0..3
            float4 v = *(const float4*)&h[(size_t)(m0 + row) * Ff + k0 + c4 * 4];
            As[c4 * 4 + 0][row] = v.x;
            As[c4 * 4 + 1][row] = v.y;
            As[c4 * 4 + 2][row] = v.z;
            As[c4 * 4 + 3][row] = v.w;
        }
        {
            int row = tid >> 4;               // 0..15
            int c4 = tid & 15;                // 0..15
            float4 v = *(const float4*)&W_s[(size_t)(k0 + row) * Ll + c4 * 4];
            *(float4*)&Bs[row][c4 * 4] = v;
        }
        __syncthreads();
        #pragma unroll
        for (int k = 0; k < BK; k++) {
            float4 a0 = *(const float4*)&As[k][ty * 8];
            float4 a1 = *(const float4*)&As[k][ty * 8 + 4];
            float4 bv = *(const float4*)&Bs[k][tx * 4];
            float a[8] = {a0.x, a0.y, a0.z, a0.w, a1.x, a1.y, a1.z, a1.w};
            float bb[4] = {bv.x, bv.y, bv.z, bv.w};
            #pragma unroll
            for (int i = 0; i < 8; i++)
                #pragma unroll
                for (int j = 0; j < 4; j++) acc[i][j] += a[i] * bb[j];
        }
        __syncthreads();
    }
    #pragma unroll
    for (int i = 0; i < 8; i++) {
        int row = m0 + ty * 8 + i;
        float id = g_inv_deg[row];
        #pragma unroll
        for (int j = 0; j < 4; j++) {
            int l = tx * 4 + j;
            g_Ys[(size_t)row * Ll + l] = acc[i][j] * id;
        }
    }
}

// ---------------- K3: h1 = elu(g @ Ys + b_s)  (batched 512x64x512) ----------------
__global__ void __launch_bounds__(256) k3_gemm(const float* __restrict__ g,
                                               const float* __restrict__ b_s) {
    __shared__ __align__(16) float As[BK][BM + 4];
    __shared__ __align__(16) float Bs[BK][BN];
    int b = blockIdx.y;
    int m0 = blockIdx.x * BM;
    const float* A = g + (size_t)b * Nn * Nn;
    const float* Bm = g_Ys + (size_t)b * Nn * Ll;
    int tid = threadIdx.x;
    int tx = tid & 15;
    int ty = tid >> 4;
    float acc[8][4];
    #pragma unroll
    for (int i = 0; i < 8; i++)
        #pragma unroll
        for (int j = 0; j < 4; j++) acc[i][j] = 0.f;

    for (int k0 = 0; k0 < Nn; k0 += BK) {
        #pragma unroll
        for (int jj = 0; jj < 2; jj++) {
            int f4 = tid + 256 * jj;
            int row = f4 >> 2;
            int c4 = f4 & 3;
            float4 v = *(const float4*)&A[(size_t)(m0 + row) * Nn + k0 + c4 * 4];
            As[c4 * 4 + 0][row] = v.x;
            As[c4 * 4 + 1][row] = v.y;
            As[c4 * 4 + 2][row] = v.z;
            As[c4 * 4 + 3][row] = v.w;
        }
        {
            int row = tid >> 4;
            int c4 = tid & 15;
            float4 v = *(const float4*)&Bm[(size_t)(k0 + row) * Ll + c4 * 4];
            *(float4*)&Bs[row][c4 * 4] = v;
        }
        __syncthreads();
        #pragma unroll
        for (int k = 0; k < BK; k++) {
            float4 a0 = *(const float4*)&As[k][ty * 8];
            float4 a1 = *(const float4*)&As[k][ty * 8 + 4];
            float4 bv = *(const float4*)&Bs[k][tx * 4];
            float a[8] = {a0.x, a0.y, a0.z, a0.w, a1.x, a1.y, a1.z, a1.w};
            float bb[4] = {bv.x, bv.y, bv.z, bv.w};
            #pragma unroll
            for (int i = 0; i < 8; i++)
                #pragma unroll
                for (int j = 0; j < 4; j++) acc[i][j] += a[i] * bb[j];
        }
        __syncthreads();
    }
    #pragma unroll
    for (int i = 0; i < 8; i++) {
        int row = m0 + ty * 8 + i;
        #pragma unroll
        for (int j = 0; j < 4; j++) {
            int l = tx * 4 + j;
            float x = acc[i][j] + b_s[l];
            g_h1[((size_t)b * Nn + row) * Ll + l] = elu1(x);
        }
    }
}

// ---------------- K4: q = (h1 @ [W_mu|W_lv]) * inv_deg  (warp per row) ------------
__global__ void k4_q(const float* __restrict__ Wmu, const float* __restrict__ Wlv) {
    int warp = (blockIdx.x * blockDim.x + threadIdx.x) >> 5;
    int lane = threadIdx.x & 31;
    if (warp >= Bb * Nn) return;
    const float* r = g_h1 + (size_t)warp * Ll;
    float a0 = r[lane], a1 = r[lane + 32];
    float pm = a0 * Wmu[lane] + a1 * Wmu[lane + 32];
    float pl = a0 * Wlv[lane] + a1 * Wlv[lane + 32];
    #pragma unroll
    for (int o = 16; o; o >>= 1) {
        pm += __shfl_down_sync(0xffffffffu, pm, o);
        pl += __shfl_down_sync(0xffffffffu, pl, o);
    }
    if (lane == 0) {
        float id = g_inv_deg[warp];
        g_q[warp] = make_float2(pm * id, pl * id);
    }
}

// ---------------- K5: mu/lv matvec + reparam + sigmoid + KL partial ----------------
__global__ void k5_muvlv(const float* __restrict__ g, const float* __restrict__ eps,
                         const float* __restrict__ bmu, const float* __restrict__ blv,
                         const float* __restrict__ beta) {
    int gwarp = (blockIdx.x * blockDim.x + threadIdx.x) >> 5;   // b*N + i
    int lane = threadIdx.x & 31;
    int wib = threadIdx.x >> 5;
    __shared__ float sred[8];
    float t = 0.f;
    if (gwarp < Bb * Nn) {
        int b = gwarp >> 9;
        const float* row = g + (size_t)gwarp * Nn;
        const float2* q = g_q + (size_t)b * Nn;
        float am = 0.f, al = 0.f;
        #pragma unroll 4
        for (int k = lane; k < Nn; k += 32) {
            float gv = row[k];
            float2 qq = q[k];
            am += gv * qq.x;
            al += gv * qq.y;
        }
        #pragma unroll
        for (int o = 16; o; o >>= 1) {
            am += __shfl_down_sync(0xffffffffu, am, o);
            al += __shfl_down_sync(0xffffffffu, al, o);
        }
        if (lane == 0) {
            float mu = elu1(am + bmu[0]);
            float lv = elu1(al + blv[0]);
            float z = mu + eps[gwarp] * expf(0.5f * lv);
            float v = 1.f / (1.f + expf(-beta[0] * z));
            g_v[gwarp] = v;
            g_vd[gwarp] = v * g_inv_deg[gwarp];
            t = 1.f + 2.f * lv - mu * mu - expf(2.f * lv);
        }
    }
    if (lane == 0) sred[wib] = t;
    __syncthreads();
    if (threadIdx.x == 0) {
        float s = 0.f;
        #pragma unroll
        for (int i = 0; i < 8; i++) s += sred[i];
        atomicAdd(&g_acc[0], s);
    }
}

// ---------------- K6: decoder matvec + rank-1 + fused MSE ----------------
__global__ void k6_dec(const float* __restrict__ g, const float* __restrict__ Wdec,
                       const float* __restrict__ bdec) {
    int gwarp = (blockIdx.x * blockDim.x + threadIdx.x) >> 5;   // b*N + i
    int lane = threadIdx.x & 31;
    int wib = threadIdx.x >> 5;
    __shared__ float sred[8];
    float s = 0.f;
    if (gwarp < Bb * Nn) {
        int b = gwarp >> 9;
        const float* row = g + (size_t)gwarp * Nn;
        const float* vd = g_vd + (size_t)b * Nn;
        float aw = 0.f;
        #pragma unroll 4
        for (int k = lane; k < Nn; k += 32) aw += row[k] * vd[k];
        #pragma unroll
        for (int o = 16; o; o >>= 1) aw += __shfl_xor_sync(0xffffffffu, aw, o);
        const float* h1r = g_h1 + (size_t)gwarp * Ll;
        #pragma unroll
        for (int l = lane; l < Ll; l += 32) {
            float dv = elu1(aw * Wdec[l] + bdec[l]);
            float diff = h1r[l] - dv;
            s += diff * diff;
        }
        #pragma unroll
        for (int o = 16; o; o >>= 1) s += __shfl_down_sync(0xffffffffu, s, o);
    }
    if (lane == 0) sred[wib] = s;
    __syncthreads();
    if (threadIdx.x == 0) {
        float t = 0.f;
        #pragma unroll
        for (int i = 0; i < 8; i++) t += sred[i];
        atomicAdd(&g_acc[1], t);
    }
}

// ---------------- K7: hp[b,l] = sum_n h1[b,n,l] * v[b,n] ----------------
__global__ void k7_pool() {
    int b = blockIdx.x;
    int l = threadIdx.x & 63;
    int seg = threadIdx.x >> 6;            // 0..3
    float s = 0.f;
    int n0 = seg * 128;
    for (int n = n0; n < n0 + 128; n++)
        s += g_h1[((size_t)b * Nn + n) * Ll + l] * g_v[b * Nn + n];
    __shared__ float sm[4][64];
    sm[seg][l] = s;
    __syncthreads();
    if (seg == 0)
        g_hp[b * Ll + l] = (sm[0][l] + sm[1][l]) + (sm[2][l] + sm[3][l]);
}

// ---------------- K8: classifier + log_softmax + nll/acc partials ----------------
__global__ void k8_cls(const float* __restrict__ W1, const float* __restrict__ b1,
                       const float* __restrict__ W2, const float* __restrict__ b2,
                       const int* __restrict__ labels) {
    int b = blockIdx.x;
    int t = threadIdx.x;                   // 128 threads
    __shared__ float hps[Ll];
    __shared__ float a1[Hh];
    __shared__ float lg[Cc];
    if (t < Ll) hps[t] = g_hp[b * Ll + t];
    __syncthreads();
    float acc = b1[t];
    #pragma unroll 8
    for (int l = 0; l < Ll; l++) acc += hps[l] * W1[l * Hh + t];
    a1[t] = elu1(acc);
    __syncthreads();
    if (t < Cc) {
        float s = b2[t];
        #pragma unroll 8
        for (int hh = 0; hh < Hh; hh++) s += a1[hh] * W2[hh * Cc + t];
        lg[t] = s;
    }
    __syncthreads();
    if (t == 0) {
        float mx = lg[0];
        int am = 0;
        #pragma unroll
        for (int c = 1; c < Cc; c++)
            if (lg[c] > mx) { mx = lg[c]; am = c; }
        float se = 0.f;
        #pragma unroll
        for (int c = 0; c < Cc; c++) se += expf(lg[c] - mx);
        float lse = mx + logf(se);
        int lab = labels[b];
        atomicAdd(&g_acc[2], -(lg[lab] - lse));
        atomicAdd(&g_acc[3], (am == lab) ? 1.f : 0.f);
    }
}

// ---------------- K9: finalize ----------------
__global__ void k9_final(float* out) {
    const float M = (float)(Bb * Nn);
    float kl = (-0.5f / M) * (g_acc[0] / M);
    float mse = g_acc[1] / (float)(Bb * Nn * Ll);
    float nll = g_acc[2] / (float)Bb;
    out[0] = nll + kl + mse;
    out[1] = g_acc[3] / (float)Bb;
}

// ---------------- launch ----------------
extern "C" void kernel_launch(void* const* d_in, const int* in_sizes, int n_in,
                              void* d_out, int out_size) {
    const float* g     = (const float*)d_in[0];
    const float* h     = (const float*)d_in[1];
    const int*   labels= (const int*)  d_in[2];
    const float* eps   = (const float*)d_in[3];
    const float* W_s   = (const float*)d_in[4];
    const float* b_s   = (const float*)d_in[5];
    const float* W_mu  = (const float*)d_in[6];
    const float* b_mu  = (const float*)d_in[7];
    const float* W_lv  = (const float*)d_in[8];
    const float* b_lv  = (const float*)d_in[9];
    const float* W_dec = (const float*)d_in[10];
    const float* b_dec = (const float*)d_in[11];
    const float* W1    = (const float*)d_in[12];
    const float* b1    = (const float*)d_in[13];
    const float* W2    = (const float*)d_in[14];
    const float* b2    = (const float*)d_in[15];
    const float* beta  = (const float*)d_in[16];
    float* out = (float*)d_out;

    k0_init<<<1, 32>>>();
    k1_deg<<<(Bb * Nn) / 256, 256>>>(g);
    k2_hws<<<(Bb * Nn) / BM, 256>>>(h, W_s);
    k3_gemm<<<dim3(Nn / BM, Bb), 256>>>(g, b_s);
    k4_q<<<(Bb * Nn * 32) / 256, 256>>>(W_mu, W_lv);
    k5_muvlv<<<(Bb * Nn * 32) / 256, 256>>>(g, eps, b_mu, b_lv, beta);
    k6_dec<<<(Bb * Nn * 32) / 256, 256>>>(g, W_dec, b_dec);
    k7_pool<<<Bb, 256>>>();
    k8_cls<<<Bb, Hh>>>(W1, b1, W2, b2, labels);
    k9_final<<<1, 1>>>(out);
}

// round 4
// speedup vs baseline: 1.0364x; 1.0364x over previous
#include <cuda_runtime.h>
#include <cuda_bf16.h>
#include <math.h>

// Problem constants
#define Bb 128
#define Nn 512
#define Ff 128
#define Ll 64
#define Hh 128
#define Cc 10

// ---------------- scratch (device globals; no allocation allowed) ----------------
__device__ float g_inv_deg[Bb * Nn];            // 1/deg[b,k]
__device__ float g_Ys[Bb * Nn * Ll];            // (h @ W_s) / deg    [B,N,L]
__device__ float g_h1[Bb * Nn * Ll];            // elu(g @ Ys + b_s)  [B,N,L]
__device__ float2 g_q[Bb * Nn];                 // (h1@W_mu, h1@W_lv)/deg
__device__ float g_v[Bb * Nn];                  // sigmoid(beta*z)
__device__ float g_vd[Bb * Nn];                 // v / deg
__device__ float g_hp[Bb * Ll];                 // pooled features
__device__ float g_acc[4];                      // [kl_sum, mse_sum, nll_sum, acc_sum]

__device__ __forceinline__ float elu1(float x) { return x > 0.f ? x : expm1f(x); }

// ---------------- K0: zero accumulators ----------------
__global__ void k0_init() {
    if (threadIdx.x < 4) g_acc[threadIdx.x] = 0.f;
}

// ---------------- K1: inverse degrees (column sums of g) ----------------
__global__ void k1_deg(const float* __restrict__ g) {
    int idx = blockIdx.x * blockDim.x + threadIdx.x;   // b*N + n
    if (idx >= Bb * Nn) return;
    int b = idx >> 9;
    int n = idx & (Nn - 1);
    const float* p = g + (size_t)b * Nn * Nn + n;
    float s0 = 0.f, s1 = 0.f, s2 = 0.f, s3 = 0.f;
    #pragma unroll 4
    for (int i = 0; i < Nn; i += 4) {
        s0 += p[(size_t)(i + 0) * Nn];
        s1 += p[(size_t)(i + 1) * Nn];
        s2 += p[(size_t)(i + 2) * Nn];
        s3 += p[(size_t)(i + 3) * Nn];
    }
    g_inv_deg[idx] = 1.f / ((s0 + s1) + (s2 + s3));
}

// ---------------- shared tiled-GEMM parameters ----------------
#define BM 128
#define BN 64
#define BK 16
// 256 threads, each computes 8(m) x 4(n)

// ---------------- K2: Ys = (h @ W_s) * inv_deg   ( [65536,128] @ [128,64] ) -------
__global__ void __launch_bounds__(256) k2_hws(const float* __restrict__ h,
                                              const float* __restrict__ W_s) {
    __shared__ __align__(16) float As[BK][BM + 4];
    __shared__ __align__(16) float Bs[BK][BN];
    int m0 = blockIdx.x * BM;           // row tile into 65536 rows
    int tid = threadIdx.x;
    int tx = tid & 15;                  // n group (4 cols each)
    int ty = tid >> 4;                  // m group (8 rows each)
    float acc[8][4];
    #pragma unroll
    for (int i = 0; i < 8; i++)
        #pragma unroll
        for (int j = 0; j < 4; j++) acc[i][j] = 0.f;

    for (int k0 = 0; k0 < Ff; k0 += BK) {
        #pragma unroll
        for (int jj = 0; jj < 2; jj++) {
            int f4 = tid + 256 * jj;          // 0..511
            int row = f4 >> 2;                // 0..127
            int c4 = f4 & 3;                  // 0..3
            float4 v = *(const float4*)&h[(size_t)(m0 + row) * Ff + k0 + c4 * 4];
            As[c4 * 4 + 0][row] = v.x;
            As[c4 * 4 + 1][row] = v.y;
            As[c4 * 4 + 2][row] = v.z;
            As[c4 * 4 + 3][row] = v.w;
        }
        {
            int row = tid >> 4;               // 0..15
            int c4 = tid & 15;                // 0..15
            float4 v = *(const float4*)&W_s[(size_t)(k0 + row) * Ll + c4 * 4];
            *(float4*)&Bs[row][c4 * 4] = v;
        }
        __syncthreads();
        #pragma unroll
        for (int k = 0; k < BK; k++) {
            float4 a0 = *(const float4*)&As[k][ty * 8];
            float4 a1 = *(const float4*)&As[k][ty * 8 + 4];
            float4 bv = *(const float4*)&Bs[k][tx * 4];
            float a[8] = {a0.x, a0.y, a0.z, a0.w, a1.x, a1.y, a1.z, a1.w};
            float bb[4] = {bv.x, bv.y, bv.z, bv.w};
            #pragma unroll
            for (int i = 0; i < 8; i++)
                #pragma unroll
                for (int j = 0; j < 4; j++) acc[i][j] += a[i] * bb[j];
        }
        __syncthreads();
    }
    #pragma unroll
    for (int i = 0; i < 8; i++) {
        int row = m0 + ty * 8 + i;
        float id = g_inv_deg[row];
        #pragma unroll
        for (int j = 0; j < 4; j++) {
            int l = tx * 4 + j;
            g_Ys[(size_t)row * Ll + l] = acc[i][j] * id;
        }
    }
}

// ---------------- K3: h1 = elu(g @ Ys + b_s)  (batched 512x64x512) ----------------
__global__ void __launch_bounds__(256) k3_gemm(const float* __restrict__ g,
                                               const float* __restrict__ b_s) {
    __shared__ __align__(16) float As[BK][BM + 4];
    __shared__ __align__(16) float Bs[BK][BN];
    int b = blockIdx.y;
    int m0 = blockIdx.x * BM;
    const float* A = g + (size_t)b * Nn * Nn;
    const float* Bm = g_Ys + (size_t)b * Nn * Ll;
    int tid = threadIdx.x;
    int tx = tid & 15;
    int ty = tid >> 4;
    float acc[8][4];
    #pragma unroll
    for (int i = 0; i < 8; i++)
        #pragma unroll
        for (int j = 0; j < 4; j++) acc[i][j] = 0.f;

    for (int k0 = 0; k0 < Nn; k0 += BK) {
        #pragma unroll
        for (int jj = 0; jj < 2; jj++) {
            int f4 = tid + 256 * jj;
            int row = f4 >> 2;
            int c4 = f4 & 3;
            float4 v = *(const float4*)&A[(size_t)(m0 + row) * Nn + k0 + c4 * 4];
            As[c4 * 4 + 0][row] = v.x;
            As[c4 * 4 + 1][row] = v.y;
            As[c4 * 4 + 2][row] = v.z;
            As[c4 * 4 + 3][row] = v.w;
        }
        {
            int row = tid >> 4;
            int c4 = tid & 15;
            float4 v = *(const float4*)&Bm[(size_t)(k0 + row) * Ll + c4 * 4];
            *(float4*)&Bs[row][c4 * 4] = v;
        }
        __syncthreads();
        #pragma unroll
        for (int k = 0; k < BK; k++) {
            float4 a0 = *(const float4*)&As[k][ty * 8];
            float4 a1 = *(const float4*)&As[k][ty * 8 + 4];
            float4 bv = *(const float4*)&Bs[k][tx * 4];
            float a[8] = {a0.x, a0.y, a0.z, a0.w, a1.x, a1.y, a1.z, a1.w};
            float bb[4] = {bv.x, bv.y, bv.z, bv.w};
            #pragma unroll
            for (int i = 0; i < 8; i++)
                #pragma unroll
                for (int j = 0; j < 4; j++) acc[i][j] += a[i] * bb[j];
        }
        __syncthreads();
    }
    #pragma unroll
    for (int i = 0; i < 8; i++) {
        int row = m0 + ty * 8 + i;
        #pragma unroll
        for (int j = 0; j < 4; j++) {
            int l = tx * 4 + j;
            float x = acc[i][j] + b_s[l];
            g_h1[((size_t)b * Nn + row) * Ll + l] = elu1(x);
        }
    }
}

// ---------------- K4: q = (h1 @ [W_mu|W_lv]) * inv_deg  (warp per row) ------------
__global__ void k4_q(const float* __restrict__ Wmu, const float* __restrict__ Wlv) {
    int warp = (blockIdx.x * blockDim.x + threadIdx.x) >> 5;
    int lane = threadIdx.x & 31;
    if (warp >= Bb * Nn) return;
    const float* r = g_h1 + (size_t)warp * Ll;
    float a0 = r[lane], a1 = r[lane + 32];
    float pm = a0 * Wmu[lane] + a1 * Wmu[lane + 32];
    float pl = a0 * Wlv[lane] + a1 * Wlv[lane + 32];
    #pragma unroll
    for (int o = 16; o; o >>= 1) {
        pm += __shfl_down_sync(0xffffffffu, pm, o);
        pl += __shfl_down_sync(0xffffffffu, pl, o);
    }
    if (lane == 0) {
        float id = g_inv_deg[warp];
        g_q[warp] = make_float2(pm * id, pl * id);
    }
}

// ---------------- K5: mu/lv matvec + reparam + sigmoid + KL partial ----------------
__global__ void k5_muvlv(const float* __restrict__ g, const float* __restrict__ eps,
                         const float* __restrict__ bmu, const float* __restrict__ blv,
                         const float* __restrict__ beta) {
    int gwarp = (blockIdx.x * blockDim.x + threadIdx.x) >> 5;   // b*N + i
    int lane = threadIdx.x & 31;
    int wib = threadIdx.x >> 5;
    __shared__ float sred[8];
    float t = 0.f;
    if (gwarp < Bb * Nn) {
        int b = gwarp >> 9;
        const float* row = g + (size_t)gwarp * Nn;
        const float2* q = g_q + (size_t)b * Nn;
        float am = 0.f, al = 0.f;
        #pragma unroll 4
        for (int k = lane; k < Nn; k += 32) {
            float gv = row[k];
            float2 qq = q[k];
            am += gv * qq.x;
            al += gv * qq.y;
        }
        #pragma unroll
        for (int o = 16; o; o >>= 1) {
            am += __shfl_down_sync(0xffffffffu, am, o);
            al += __shfl_down_sync(0xffffffffu, al, o);
        }
        if (lane == 0) {
            float mu = elu1(am + bmu[0]);
            float lv = elu1(al + blv[0]);
            float z = mu + eps[gwarp] * expf(0.5f * lv);
            float v = 1.f / (1.f + expf(-beta[0] * z));
            g_v[gwarp] = v;
            g_vd[gwarp] = v * g_inv_deg[gwarp];
            t = 1.f + 2.f * lv - mu * mu - expf(2.f * lv);
        }
    }
    if (lane == 0) sred[wib] = t;
    __syncthreads();
    if (threadIdx.x == 0) {
        float s = 0.f;
        #pragma unroll
        for (int i = 0; i < 8; i++) s += sred[i];
        atomicAdd(&g_acc[0], s);
    }
}

// ---------------- K6: decoder matvec + rank-1 + fused MSE ----------------
__global__ void k6_dec(const float* __restrict__ g, const float* __restrict__ Wdec,
                       const float* __restrict__ bdec) {
    int gwarp = (blockIdx.x * blockDim.x + threadIdx.x) >> 5;   // b*N + i
    int lane = threadIdx.x & 31;
    int wib = threadIdx.x >> 5;
    __shared__ float sred[8];
    float s = 0.f;
    if (gwarp < Bb * Nn) {
        int b = gwarp >> 9;
        const float* row = g + (size_t)gwarp * Nn;
        const float* vd = g_vd + (size_t)b * Nn;
        float aw = 0.f;
        #pragma unroll 4
        for (int k = lane; k < Nn; k += 32) aw += row[k] * vd[k];
        #pragma unroll
        for (int o = 16; o; o >>= 1) aw += __shfl_xor_sync(0xffffffffu, aw, o);
        const float* h1r = g_h1 + (size_t)gwarp * Ll;
        #pragma unroll
        for (int l = lane; l < Ll; l += 32) {
            float dv = elu1(aw * Wdec[l] + bdec[l]);
            float diff = h1r[l] - dv;
            s += diff * diff;
        }
        #pragma unroll
        for (int o = 16; o; o >>= 1) s += __shfl_down_sync(0xffffffffu, s, o);
    }
    if (lane == 0) sred[wib] = s;
    __syncthreads();
    if (threadIdx.x == 0) {
        float t = 0.f;
        #pragma unroll
        for (int i = 0; i < 8; i++) t += sred[i];
        atomicAdd(&g_acc[1], t);
    }
}

// ---------------- K7: hp[b,l] = sum_n h1[b,n,l] * v[b,n] ----------------
__global__ void k7_pool() {
    int b = blockIdx.x;
    int l = threadIdx.x & 63;
    int seg = threadIdx.x >> 6;            // 0..3
    float s = 0.f;
    int n0 = seg * 128;
    for (int n = n0; n < n0 + 128; n++)
        s += g_h1[((size_t)b * Nn + n) * Ll + l] * g_v[b * Nn + n];
    __shared__ float sm[4][64];
    sm[seg][l] = s;
    __syncthreads();
    if (seg == 0)
        g_hp[b * Ll + l] = (sm[0][l] + sm[1][l]) + (sm[2][l] + sm[3][l]);
}

// ---------------- K8: classifier + log_softmax + nll/acc partials ----------------
__global__ void k8_cls(const float* __restrict__ W1, const float* __restrict__ b1,
                       const float* __restrict__ W2, const float* __restrict__ b2,
                       const int* __restrict__ labels) {
    int b = blockIdx.x;
    int t = threadIdx.x;                   // 128 threads
    __shared__ float hps[Ll];
    __shared__ float a1[Hh];
    __shared__ float lg[Cc];
    if (t < Ll) hps[t] = g_hp[b * Ll + t];
    __syncthreads();
    float acc = b1[t];
    #pragma unroll 8
    for (int l = 0; l < Ll; l++) acc += hps[l] * W1[l * Hh + t];
    a1[t] = elu1(acc);
    __syncthreads();
    if (t < Cc) {
        float s = b2[t];
        #pragma unroll 8
        for (int hh = 0; hh < Hh; hh++) s += a1[hh] * W2[hh * Cc + t];
        lg[t] = s;
    }
    __syncthreads();
    if (t == 0) {
        float mx = lg[0];
        int am = 0;
        #pragma unroll
        for (int c = 1; c < Cc; c++)
            if (lg[c] > mx) { mx = lg[c]; am = c; }
        float se = 0.f;
        #pragma unroll
        for (int c = 0; c < Cc; c++) se += expf(lg[c] - mx);
        float lse = mx + logf(se);
        int lab = labels[b];
        atomicAdd(&g_acc[2], -(lg[lab] - lse));
        atomicAdd(&g_acc[3], (am == lab) ? 1.f : 0.f);
    }
}

// ---------------- K9: finalize ----------------
__global__ void k9_final(float* out) {
    const float M = (float)(Bb * Nn);
    float kl = (-0.5f / M) * (g_acc[0] / M);
    float mse = g_acc[1] / (float)(Bb * Nn * Ll);
    float nll = g_acc[2] / (float)Bb;
    out[0] = nll + kl + mse;
    out[1] = g_acc[3] / (float)Bb;
}

// ---------------- launch ----------------
extern "C" void kernel_launch(void* const* d_in, const int* in_sizes, int n_in,
                              void* d_out, int out_size) {
    const float* g     = (const float*)d_in[0];
    const float* h     = (const float*)d_in[1];
    const int*   labels= (const int*)  d_in[2];
    const float* eps   = (const float*)d_in[3];
    const float* W_s   = (const float*)d_in[4];
    const float* b_s   = (const float*)d_in[5];
    const float* W_mu  = (const float*)d_in[6];
    const float* b_mu  = (const float*)d_in[7];
    const float* W_lv  = (const float*)d_in[8];
    const float* b_lv  = (const float*)d_in[9];
    const float* W_dec = (const float*)d_in[10];
    const float* b_dec = (const float*)d_in[11];
    const float* W1    = (const float*)d_in[12];
    const float* b1    = (const float*)d_in[13];
    const float* W2    = (const float*)d_in[14];
    const float* b2    = (const float*)d_in[15];
    const float* beta  = (const float*)d_in[16];
    float* out = (float*)d_out;

    k0_init<<<1, 32>>>();
    k1_deg<<<(Bb * Nn) / 256, 256>>>(g);
    k2_hws<<<(Bb * Nn) / BM, 256>>>(h, W_s);
    k3_gemm<<<dim3(Nn / BM, Bb), 256>>>(g, b_s);
    k4_q<<<(Bb * Nn * 32) / 256, 256>>>(W_mu, W_lv);
    k5_muvlv<<<(Bb * Nn * 32) / 256, 256>>>(g, eps, b_mu, b_lv, beta);
    k6_dec<<<(Bb * Nn * 32) / 256, 256>>>(g, W_dec, b_dec);
    k7_pool<<<Bb, 256>>>();
    k8_cls<<<Bb, Hh>>>(W1, b1, W2, b2, labels);
    k9_final<<<1, 1>>>(out);
}